// round 1
// baseline (speedup 1.0000x reference)
#include <cuda_runtime.h>
#include <cuda_bf16.h>

// Fused GNN: encoder GraphConv((1,8)->8) + predictor GraphConv(8->8) + decoder
// GraphConv((8,1)->1), fixed tiny graphs folded into closed-form per-element math.
//
// Per element b:
//   s[j]   = sum_{d=-3..2} x[(4j+d) mod 40]                       (A_ENC)
//   z1[j,f]= relu(s[j]*ew[f] + eb[f] + sum_g z[j,g]*WR[f,g])
//   n[j]   = z1[j-1] + z1[j+1]  (ring mod 10)                      (A_PRED stencil)
//   pre2   = z1 @ WA^T + n @ WB^T + pb,  WA=Wrel+Wroot, WB=w*Wrel, w=exp(-1/9)
//   t[j]   = relu(pre2[j]) . dw                                    (decoder rel folded)
//   out[i] = t[jlo(i)] (+ t[jhi(i)]) + db + dr*y[i]                (A_DEC all-ones)

__global__ void __launch_bounds__(128) gnn_fused_kernel(
    const float* __restrict__ x,
    const float* __restrict__ z,
    const float* __restrict__ y,
    const float* __restrict__ enc_rel_w,
    const float* __restrict__ enc_rel_b,
    const float* __restrict__ enc_root_w,
    const float* __restrict__ pred_rel_w,
    const float* __restrict__ pred_rel_b,
    const float* __restrict__ pred_root_w,
    const float* __restrict__ dec_rel_w,
    const float* __restrict__ dec_rel_b,
    const float* __restrict__ dec_root_w,
    float* __restrict__ out,
    int B)
{
    __shared__ float sWR[64];   // enc_root_w[f][g]
    __shared__ float sWA[64];   // pred_rel_w + pred_root_w
    __shared__ float sWB[64];   // w_edge * pred_rel_w
    __shared__ float sEW[8], sEB[8], sPB[8], sDW[8];
    __shared__ float sDB, sDR;

    const int tid = threadIdx.x;
    if (tid < 64) {
        sWR[tid] = enc_root_w[tid];
        float pr = pred_rel_w[tid];
        sWA[tid] = pr + pred_root_w[tid];
        sWB[tid] = expf(-1.0f / 9.0f) * pr;   // np.float32(np.exp(-(1/3)^2))
    }
    if (tid < 8) {
        sEW[tid] = enc_rel_w[tid];
        sEB[tid] = enc_rel_b[tid];
        sPB[tid] = pred_rel_b[tid];
        sDW[tid] = dec_rel_w[tid];
    }
    if (tid == 0) { sDB = dec_rel_b[0]; sDR = dec_root_w[0]; }
    __syncthreads();

    const long long b = (long long)blockIdx.x * blockDim.x + tid;
    if (b >= B) return;

    // ---------- load x (40 floats), compute s[10] ----------
    float xa[40];
    {
        const float4* xp = reinterpret_cast<const float4*>(x + b * 40);
        #pragma unroll
        for (int i = 0; i < 10; i++) {
            float4 v = xp[i];
            xa[4*i+0] = v.x; xa[4*i+1] = v.y; xa[4*i+2] = v.z; xa[4*i+3] = v.w;
        }
    }
    float s[10];
    #pragma unroll
    for (int j = 0; j < 10; j++) {
        float a0 = xa[(4*j + 37) % 40] + xa[(4*j + 38) % 40];
        float a1 = xa[(4*j + 39) % 40] + xa[(4*j +  0) % 40];
        float a2 = xa[(4*j +  1) % 40] + xa[(4*j +  2) % 40];
        s[j] = (a0 + a1) + a2;
    }

    // ---------- load z (80 floats) ----------
    float za[80];
    {
        const float4* zp = reinterpret_cast<const float4*>(z + b * 80);
        #pragma unroll
        for (int i = 0; i < 20; i++) {
            float4 v = zp[i];
            za[4*i+0] = v.x; za[4*i+1] = v.y; za[4*i+2] = v.z; za[4*i+3] = v.w;
        }
    }

    // ---------- encoder: z1[j][f] ----------
    float z1[80];
    #pragma unroll
    for (int f = 0; f < 8; f++) {
        float wr[8];
        #pragma unroll
        for (int g = 0; g < 8; g++) wr[g] = sWR[f*8 + g];
        const float ew = sEW[f], eb = sEB[f];
        #pragma unroll
        for (int j = 0; j < 10; j++) {
            float accA = fmaf(s[j], ew, eb);
            float accB = 0.0f;
            #pragma unroll
            for (int g = 0; g < 4; g++) accA = fmaf(za[j*8 + g],     wr[g],     accA);
            #pragma unroll
            for (int g = 0; g < 4; g++) accB = fmaf(za[j*8 + 4 + g], wr[4 + g], accB);
            z1[j*8 + f] = fmaxf(accA + accB, 0.0f);
        }
    }

    // ---------- ring neighbor sums ----------
    float nn[80];
    #pragma unroll
    for (int j = 0; j < 10; j++) {
        const int jm = (j + 9) % 10, jp = (j + 1) % 10;
        #pragma unroll
        for (int g = 0; g < 8; g++) nn[j*8 + g] = z1[jm*8 + g] + z1[jp*8 + g];
    }

    // ---------- predictor + decoder-rel fused: t[10] ----------
    float t[10];
    #pragma unroll
    for (int j = 0; j < 10; j++) t[j] = 0.0f;

    #pragma unroll
    for (int f = 0; f < 8; f++) {
        float wa[8], wb[8];
        #pragma unroll
        for (int g = 0; g < 8; g++) { wa[g] = sWA[f*8 + g]; wb[g] = sWB[f*8 + g]; }
        const float pb = sPB[f], dw = sDW[f];
        #pragma unroll
        for (int j = 0; j < 10; j++) {
            float accA = pb;
            float accB = 0.0f;
            #pragma unroll
            for (int g = 0; g < 8; g++) accA = fmaf(z1[j*8 + g], wa[g], accA);
            #pragma unroll
            for (int g = 0; g < 8; g++) accB = fmaf(nn[j*8 + g], wb[g], accB);
            t[j] = fmaf(fmaxf(accA + accB, 0.0f), dw, t[j]);
        }
    }

    // ---------- decoder aggregation + root + output ----------
    const float dB = sDB, dR = sDR;
    const float4* yp = reinterpret_cast<const float4*>(y + b * 40);
    float4* op = reinterpret_cast<float4*>(out + b * 40);
    #pragma unroll
    for (int q = 0; q < 10; q++) {
        float4 yv = yp[q];
        float r[4];
        float yc[4] = {yv.x, yv.y, yv.z, yv.w};
        #pragma unroll
        for (int c = 0; c < 4; c++) {
            const int i = 4*q + c;
            const int jlo = ((i + 1) / 4) % 10;   // ceil((i-2)/4) mod 10
            const int jhi = ((i + 3) / 4) % 10;   // floor((i+3)/4) mod 10
            float agg = t[jlo];
            if (jhi != jlo) agg += t[jhi];
            r[c] = fmaf(yc[c], dR, agg + dB);
        }
        op[q] = make_float4(r[0], r[1], r[2], r[3]);
    }
}

extern "C" void kernel_launch(void* const* d_in, const int* in_sizes, int n_in,
                              void* d_out, int out_size) {
    const float* x           = (const float*)d_in[0];
    const float* z           = (const float*)d_in[1];
    const float* y           = (const float*)d_in[2];
    const float* enc_rel_w   = (const float*)d_in[3];
    const float* enc_rel_b   = (const float*)d_in[4];
    const float* enc_root_w  = (const float*)d_in[5];
    const float* pred_rel_w  = (const float*)d_in[6];
    const float* pred_rel_b  = (const float*)d_in[7];
    const float* pred_root_w = (const float*)d_in[8];
    const float* dec_rel_w   = (const float*)d_in[9];
    const float* dec_rel_b   = (const float*)d_in[10];
    const float* dec_root_w  = (const float*)d_in[11];
    float* out = (float*)d_out;

    const int B = in_sizes[0] / 40;
    const int threads = 128;
    const int blocks = (B + threads - 1) / threads;
    gnn_fused_kernel<<<blocks, threads>>>(
        x, z, y, enc_rel_w, enc_rel_b, enc_root_w,
        pred_rel_w, pred_rel_b, pred_root_w,
        dec_rel_w, dec_rel_b, dec_root_w, out, B);
}